// round 5
// baseline (speedup 1.0000x reference)
#include <cuda_runtime.h>
#include <math.h>
#include <stdint.h>

typedef unsigned long long ull;

// Scratch: projected inputs [t][b][768] (xz cols 0..511 incl bias, xh cols 512..767)
__device__ float g_xzh[131072 * 768];  // 402 MB static scratch

// ---------------------------------------------------------------------------
// helpers
// ---------------------------------------------------------------------------
__device__ __forceinline__ ull dup2f(float x) {
    ull r; asm("mov.b64 %0, {%1, %1};" : "=l"(r) : "f"(x)); return r;
}
__device__ __forceinline__ ull pack2f(float x, float y) {
    ull r; asm("mov.b64 %0, {%1, %2};" : "=l"(r) : "f"(x), "f"(y)); return r;
}
__device__ __forceinline__ void unpack2(ull v, float& x, float& y) {
    asm("mov.b64 {%0, %1}, %2;" : "=f"(x), "=f"(y) : "l"(v));
}
__device__ __forceinline__ void ffma2(ull& d, ull a, ull b) {
    asm("fma.rn.f32x2 %0, %1, %2, %0;" : "+l"(d) : "l"(a), "l"(b));
}
__device__ __forceinline__ uint32_t smem_u32(const void* p) {
    return (uint32_t)__cvta_generic_to_shared(p);
}
__device__ __forceinline__ uint32_t mapa_rank(uint32_t addr, uint32_t rank) {
    uint32_t r; asm("mapa.shared::cluster.u32 %0, %1, %2;" : "=r"(r) : "r"(addr), "r"(rank));
    return r;
}
__device__ __forceinline__ void st_cluster_u64(uint32_t addr, ull v) {
    asm volatile("st.shared::cluster.b64 [%0], %1;" :: "r"(addr), "l"(v) : "memory");
}
__device__ __forceinline__ void cluster_sync_() {
    asm volatile("barrier.cluster.arrive.aligned;" ::: "memory");
    asm volatile("barrier.cluster.wait.aligned;" ::: "memory");
}
__device__ __forceinline__ float sigf(float x) {
    return __fdividef(1.f, 1.f + __expf(-x));
}
__device__ __forceinline__ float tanhfast(float x) {
    float a = fabsf(x);
    float e = __expf(2.f * a);
    float r = 1.f - __fdividef(2.f, e + 1.f);
    return copysignf(r, x);
}

// ---------------------------------------------------------------------------
// Kernel 1: projection GEMM (f32x2 microtile), unchanged from R4 (measured OK)
// ---------------------------------------------------------------------------
__global__ __launch_bounds__(256, 2) void proj_gemm(
    const float* __restrict__ x,
    const float* __restrict__ Wzr,
    const float* __restrict__ Wh,
    const float* __restrict__ bzr,
    const float* __restrict__ bh)
{
    __shared__ float As[128][16];
    __shared__ float Bs[16][128];

    const int tid = threadIdx.x;
    const int tm = tid >> 4;
    const int tn = tid & 15;
    const int Mbase = blockIdx.y * 128;
    const int Nbase = blockIdx.x * 128;

    const bool isZr = (Nbase < 512);
    const float* __restrict__ W = isZr ? Wzr : Wh;
    const int ldw  = isZr ? 512 : 256;
    const int wcol = isZr ? Nbase : (Nbase - 512);

    ull acc2[8][4];
    #pragma unroll
    for (int i = 0; i < 8; i++)
        #pragma unroll
        for (int p = 0; p < 4; p++) acc2[i][p] = 0ull;

    const int ra = tid >> 2;
    const int ka = (tid & 3) << 2;
    const int rb = tid >> 5;
    const int nb = (tid & 31) << 2;

    for (int kt = 0; kt < 256; kt += 16) {
        float4 a0 = *(const float4*)&x[(size_t)(Mbase + ra)      * 256 + kt + ka];
        float4 a1 = *(const float4*)&x[(size_t)(Mbase + ra + 64) * 256 + kt + ka];
        float4 w0 = *(const float4*)&W[(size_t)(kt + rb)     * ldw + wcol + nb];
        float4 w1 = *(const float4*)&W[(size_t)(kt + rb + 8) * ldw + wcol + nb];
        __syncthreads();
        *(float4*)&As[ra][ka]      = a0;
        *(float4*)&As[ra + 64][ka] = a1;
        *(float4*)&Bs[rb][nb]      = w0;
        *(float4*)&Bs[rb + 8][nb]  = w1;
        __syncthreads();
        #pragma unroll
        for (int kk = 0; kk < 16; kk++) {
            ulonglong2 b01 = *(const ulonglong2*)&Bs[kk][tn * 8];
            ulonglong2 b23 = *(const ulonglong2*)&Bs[kk][tn * 8 + 4];
            #pragma unroll
            for (int i = 0; i < 8; i++) {
                ull ad = dup2f(As[tm * 8 + i][kk]);
                ffma2(acc2[i][0], ad, b01.x);
                ffma2(acc2[i][1], ad, b01.y);
                ffma2(acc2[i][2], ad, b23.x);
                ffma2(acc2[i][3], ad, b23.y);
            }
        }
    }

    float bias[8];
    #pragma unroll
    for (int jj = 0; jj < 8; jj++) {
        int c = Nbase + tn * 8 + jj;
        bias[jj] = (c < 512) ? bzr[c] : bh[c - 512];
    }

    #pragma unroll
    for (int i = 0; i < 8; i++) {
        int r = Mbase + tm * 8 + i;   // r = b*1024 + t
        int b = r >> 10;
        int t = r & 1023;
        float* dst = &g_xzh[(size_t)((t << 7) + b) * 768 + Nbase + tn * 8];
        float c[8];
        #pragma unroll
        for (int p = 0; p < 4; p++) unpack2(acc2[i][p], c[2 * p], c[2 * p + 1]);
        float4 v0, v1;
        v0.x = c[0] + bias[0]; v0.y = c[1] + bias[1];
        v0.z = c[2] + bias[2]; v0.w = c[3] + bias[3];
        v1.x = c[4] + bias[4]; v1.y = c[5] + bias[5];
        v1.z = c[6] + bias[6]; v1.w = c[7] + bias[7];
        *(float4*)dst       = v0;
        *(float4*)(dst + 4) = v1;
    }
}

// ---------------------------------------------------------------------------
// Kernel 2: GRU recurrence, 16 clusters x 8 CTAs x 512 threads.
// Cluster owns 8 batch rows (4 f32x2 row-pairs). CTA rank r holds
//   U_zr cols [64r, 64r+64)  (64 KB)  and  U_h cols [32r, 32r+32)  (32 KB).
// Per step: phase1 (z slice) -> DSMEM route Z / broadcast R*h -> cluster sync
//        -> phase2 (S slice) -> combine -> DSMEM broadcast h_new -> cluster sync.
// 16 warps: warp = 16-k slice, lane = column(s).
// ---------------------------------------------------------------------------
// smem layout (bytes):
#define OFF_WZR 0         // float2[256][32]  64 KB   U_zr slice, k-major
#define OFF_WH  65536     // float [256][32]  32 KB   U_h  slice, k-major
#define OFF_P   98304     // ull   partials   32 KB   (p1: [4][16][64], p2: [4][16][32])
#define OFF_H   131072    // ull   [256][4]    8 KB   h     (f32x2 row-pairs per col)
#define OFF_RH  139264    // ull   [256][4]    8 KB   R*h
#define OFF_Z   147456    // ull   [32][4]     1 KB   Z slice for this CTA's S cols
#define OFF_XZ  148480    // float [64][8]     2 KB   xz slice [col][row]
#define OFF_XH  150528    // float [32][8]     1 KB   xh slice [col][row]
#define SMEM_BYTES 151808

extern "C" __global__ void __launch_bounds__(512, 1) __cluster_dims__(8, 1, 1)
gru_recur8(const float* __restrict__ Uzr,
           const float* __restrict__ Uh,
           float* __restrict__ out)
{
    extern __shared__ char smem[];
    float2* wzr_s = (float2*)(smem + OFF_WZR);
    float*  wh_s  = (float*)(smem + OFF_WH);
    ull*    p_s   = (ull*)(smem + OFF_P);
    ull*    h_u   = (ull*)(smem + OFF_H);
    ull*    rh_u  = (ull*)(smem + OFF_RH);
    ull*    z_u   = (ull*)(smem + OFF_Z);
    float*  xz_s  = (float*)(smem + OFF_XZ);
    float*  xh_s  = (float*)(smem + OFF_XH);

    const int tid  = threadIdx.x;
    const int wid  = tid >> 5;        // 0..15
    const int lane = tid & 31;
    const uint32_t crank = blockIdx.x & 7;
    const int r0 = (blockIdx.x >> 3) * 8;   // first batch row of cluster

    // ---- prologue: weight slices -> smem, h = 0 ----
    {
        const float2* Uzr2g = (const float2*)Uzr;   // [256][256] float2 view
        #pragma unroll 4
        for (int idx = tid; idx < 8192; idx += 512)
            wzr_s[idx] = Uzr2g[(idx >> 5) * 256 + crank * 32 + (idx & 31)];
        #pragma unroll 4
        for (int idx = tid; idx < 8192; idx += 512)
            wh_s[idx] = Uh[(idx >> 5) * 256 + crank * 32 + (idx & 31)];
        for (int idx = tid; idx < 1024; idx += 512) h_u[idx] = 0ull;
    }
    __syncthreads();
    cluster_sync_();

    // DSMEM peer addresses
    uint32_t rh_base = smem_u32(rh_u), h_base = smem_u32(h_u), z_base = smem_u32(z_u);
    uint32_t rh_r[8], h_r[8];
    #pragma unroll
    for (uint32_t r = 0; r < 8; r++) {
        rh_r[r] = mapa_rank(rh_base, r);
        h_r[r]  = mapa_rank(h_base, r);
    }

    // per-thread input-slice coords
    const int zrow = tid >> 6, zcol = tid & 63;            // all 512 threads
    const int hrow = (tid & 255) >> 5, hcol = tid & 31;    // threads < 256

    for (int t = 0; t < 1024; t++) {
        // ---- prefetch this step's xz / xh (DRAM; consumed after phase1) ----
        const size_t tb = (size_t)((t << 7) + r0) * 768;
        float xzv = g_xzh[tb + (size_t)zrow * 768 + crank * 64 + zcol];
        float xhv = 0.f;
        if (tid < 256)
            xhv = g_xzh[tb + (size_t)hrow * 768 + 512 + crank * 32 + hcol];

        // ---- phase 1: partial z[8 rows][64 local cols]; warp wid: k in [16w,16w+16) ----
        ull a[2][4];
        #pragma unroll
        for (int c = 0; c < 2; c++)
            #pragma unroll
            for (int p = 0; p < 4; p++) a[c][p] = 0ull;
        {
            const float2* wp = wzr_s + wid * 16 * 32 + lane;
            const ull*    hp = h_u + wid * 16 * 4;
            #pragma unroll
            for (int kk = 0; kk < 16; kk++) {
                float2 w = wp[kk * 32];
                ulonglong2 h01 = *(const ulonglong2*)(hp + kk * 4);
                ulonglong2 h23 = *(const ulonglong2*)(hp + kk * 4 + 2);
                ull w0 = dup2f(w.x), w1 = dup2f(w.y);
                ffma2(a[0][0], w0, h01.x); ffma2(a[0][1], w0, h01.y);
                ffma2(a[0][2], w0, h23.x); ffma2(a[0][3], w0, h23.y);
                ffma2(a[1][0], w1, h01.x); ffma2(a[1][1], w1, h01.y);
                ffma2(a[1][2], w1, h23.x); ffma2(a[1][3], w1, h23.y);
            }
        }
        #pragma unroll
        for (int p = 0; p < 4; p++) {
            ulonglong2 v; v.x = a[0][p]; v.y = a[1][p];
            *(ulonglong2*)&p_s[(p * 16 + wid) * 64 + 2 * lane] = v;  // cols 2l,2l+1
        }
        // stage inputs (store late so LDG latency overlapped phase1)
        xz_s[zcol * 8 + zrow] = xzv;
        if (tid < 256) xh_s[hcol * 8 + hrow] = xhv;
        __syncthreads();

        // ---- reduce1 + gates + DSMEM routing (threads < 256: col, rowpair) ----
        if (tid < 256) {
            const int col = tid & 63;       // local z col
            const int p   = tid >> 6;       // row pair
            float sx = 0.f, sy = 0.f;
            const ull* pp = p_s + p * 16 * 64 + col;
            #pragma unroll
            for (int w = 0; w < 16; w++) {
                float ax, ay; unpack2(pp[w * 64], ax, ay);
                sx += ax; sy += ay;
            }
            float2 xz2 = *(const float2*)&xz_s[col * 8 + 2 * p];
            sx += xz2.x; sy += xz2.y;
            float gx = sigf(sx), gy = sigf(sy);
            if (crank < 4) {
                // update gate Z: route to the CTA owning these S columns
                uint32_t dest = 2 * crank + (uint32_t)(col >> 5);
                uint32_t addr = mapa_rank(z_base, dest) + ((col & 31) * 4 + p) * 8;
                st_cluster_u64(addr, pack2f(gx, gy));
            } else {
                // reset gate R: rh = R .* h, broadcast to all 8 CTAs
                int ch = 64 * ((int)crank - 4) + col;        // hidden col
                float hx, hy; unpack2(h_u[ch * 4 + p], hx, hy);
                ull rv = pack2f(gx * hx, gy * hy);
                uint32_t off = (uint32_t)(ch * 4 + p) * 8;
                #pragma unroll
                for (uint32_t r = 0; r < 8; r++)
                    st_cluster_u64(rh_r[r] + off, rv);
            }
        }
        cluster_sync_();

        // ---- phase 2: partial S[8 rows][32 local cols] ----
        ull b[4] = {0ull, 0ull, 0ull, 0ull};
        {
            const float* wp2 = wh_s + wid * 16 * 32 + lane;
            const ull*   rp  = rh_u + wid * 16 * 4;
            #pragma unroll
            for (int kk = 0; kk < 16; kk++) {
                float w = wp2[kk * 32];
                ulonglong2 r01 = *(const ulonglong2*)(rp + kk * 4);
                ulonglong2 r23 = *(const ulonglong2*)(rp + kk * 4 + 2);
                ull wd = dup2f(w);
                ffma2(b[0], wd, r01.x); ffma2(b[1], wd, r01.y);
                ffma2(b[2], wd, r23.x); ffma2(b[3], wd, r23.y);
            }
        }
        #pragma unroll
        for (int p = 0; p < 4; p++)
            p_s[(p * 16 + wid) * 32 + lane] = b[p];
        __syncthreads();

        // ---- reduce2 + combine + h broadcast (threads < 128: col, rowpair) ----
        if (tid < 128) {
            const int col = tid & 31;       // local S col
            const int p   = tid >> 5;       // row pair
            float sx = 0.f, sy = 0.f;
            const ull* pp = p_s + p * 16 * 32 + col;
            #pragma unroll
            for (int w = 0; w < 16; w++) {
                float ax, ay; unpack2(pp[w * 32], ax, ay);
                sx += ax; sy += ay;
            }
            float2 xh2 = *(const float2*)&xh_s[col * 8 + 2 * p];
            float Sx = tanhfast(sx + xh2.x);
            float Sy = tanhfast(sy + xh2.y);
            float Zx, Zy; unpack2(z_u[col * 4 + p], Zx, Zy);
            int gcol = 32 * (int)crank + col;
            float hx, hy; unpack2(h_u[gcol * 4 + p], hx, hy);
            float hnx = fmaf(Zx, Sx - hx, hx);
            float hny = fmaf(Zy, Sy - hy, hy);
            ull hv = pack2f(hnx, hny);
            uint32_t off = (uint32_t)(gcol * 4 + p) * 8;
            #pragma unroll
            for (uint32_t r = 0; r < 8; r++)
                st_cluster_u64(h_r[r] + off, hv);
        }
        cluster_sync_();
    }

    // ---- epilogue: rank 0 writes the 8 rows ----
    if (crank == 0) {
        const int col = tid & 255;
        const int p0  = tid >> 8;           // 0..1 -> handles pairs p0 and p0+2
        #pragma unroll
        for (int q = 0; q < 2; q++) {
            int p = p0 + 2 * q;
            float hx, hy; unpack2(h_u[col * 4 + p], hx, hy);
            out[(r0 + 2 * p)     * 256 + col] = hx;
            out[(r0 + 2 * p + 1) * 256 + col] = hy;
        }
    }
}

// ---------------------------------------------------------------------------
extern "C" void kernel_launch(void* const* d_in, const int* in_sizes, int n_in,
                              void* d_out, int out_size)
{
    (void)in_sizes; (void)n_in; (void)out_size;
    const float* x   = (const float*)d_in[0];
    const float* Wzr = (const float*)d_in[1];
    const float* Uzr = (const float*)d_in[2];
    const float* bzr = (const float*)d_in[3];
    const float* Wh  = (const float*)d_in[4];
    const float* Uh  = (const float*)d_in[5];
    const float* bh  = (const float*)d_in[6];

    dim3 ggrid(6, 1024);
    proj_gemm<<<ggrid, 256>>>(x, Wzr, Wh, bzr, bh);

    cudaFuncSetAttribute(gru_recur8,
                         cudaFuncAttributeMaxDynamicSharedMemorySize, SMEM_BYTES);
    gru_recur8<<<128, 512, SMEM_BYTES>>>(Uzr, Uh, (float*)d_out);
}

// round 6
// speedup vs baseline: 2.5354x; 2.5354x over previous
#include <cuda_runtime.h>
#include <math.h>
#include <stdint.h>

typedef unsigned long long ull;

// Scratch: projected inputs [t][b][768] (xz cols 0..511 incl bias, xh cols 512..767)
__device__ float g_xzh[131072 * 768];  // 402 MB static scratch

// ---------------------------------------------------------------------------
// helpers
// ---------------------------------------------------------------------------
__device__ __forceinline__ ull dup2f(float x) {
    ull r; asm("mov.b64 %0, {%1, %1};" : "=l"(r) : "f"(x)); return r;
}
__device__ __forceinline__ void unpack2(ull v, float& x, float& y) {
    asm("mov.b64 {%0, %1}, %2;" : "=f"(x), "=f"(y) : "l"(v));
}
__device__ __forceinline__ void ffma2(ull& d, ull a, ull b) {
    asm("fma.rn.f32x2 %0, %1, %2, %0;" : "+l"(d) : "l"(a), "l"(b));
}
__device__ __forceinline__ uint32_t smem_u32(const void* p) {
    return (uint32_t)__cvta_generic_to_shared(p);
}
__device__ __forceinline__ uint32_t mapa_rank(uint32_t addr, uint32_t rank) {
    uint32_t r; asm("mapa.shared::cluster.u32 %0, %1, %2;" : "=r"(r) : "r"(addr), "r"(rank));
    return r;
}
__device__ __forceinline__ void st_cluster_f4(uint32_t addr, float4 v) {
    asm volatile("st.shared::cluster.v4.f32 [%0], {%1,%2,%3,%4};"
                 :: "r"(addr), "f"(v.x), "f"(v.y), "f"(v.z), "f"(v.w) : "memory");
}
__device__ __forceinline__ void cluster_sync_() {
    asm volatile("barrier.cluster.arrive.aligned;" ::: "memory");
    asm volatile("barrier.cluster.wait.aligned;" ::: "memory");
}
__device__ __forceinline__ float sigf(float x) {
    return __fdividef(1.f, 1.f + __expf(-x));
}
__device__ __forceinline__ float tanhfast(float x) {
    float a = fabsf(x);
    float e = __expf(2.f * a);
    float r = 1.f - __fdividef(2.f, e + 1.f);
    return copysignf(r, x);
}

// ---------------------------------------------------------------------------
// Kernel 1: projection GEMM (f32x2 microtile), unchanged (measured ~1.1 ms)
// ---------------------------------------------------------------------------
__global__ __launch_bounds__(256, 2) void proj_gemm(
    const float* __restrict__ x,
    const float* __restrict__ Wzr,
    const float* __restrict__ Wh,
    const float* __restrict__ bzr,
    const float* __restrict__ bh)
{
    __shared__ float As[128][16];
    __shared__ float Bs[16][128];

    const int tid = threadIdx.x;
    const int tm = tid >> 4;
    const int tn = tid & 15;
    const int Mbase = blockIdx.y * 128;
    const int Nbase = blockIdx.x * 128;

    const bool isZr = (Nbase < 512);
    const float* __restrict__ W = isZr ? Wzr : Wh;
    const int ldw  = isZr ? 512 : 256;
    const int wcol = isZr ? Nbase : (Nbase - 512);

    ull acc2[8][4];
    #pragma unroll
    for (int i = 0; i < 8; i++)
        #pragma unroll
        for (int p = 0; p < 4; p++) acc2[i][p] = 0ull;

    const int ra = tid >> 2;
    const int ka = (tid & 3) << 2;
    const int rb = tid >> 5;
    const int nb = (tid & 31) << 2;

    for (int kt = 0; kt < 256; kt += 16) {
        float4 a0 = *(const float4*)&x[(size_t)(Mbase + ra)      * 256 + kt + ka];
        float4 a1 = *(const float4*)&x[(size_t)(Mbase + ra + 64) * 256 + kt + ka];
        float4 w0 = *(const float4*)&W[(size_t)(kt + rb)     * ldw + wcol + nb];
        float4 w1 = *(const float4*)&W[(size_t)(kt + rb + 8) * ldw + wcol + nb];
        __syncthreads();
        *(float4*)&As[ra][ka]      = a0;
        *(float4*)&As[ra + 64][ka] = a1;
        *(float4*)&Bs[rb][nb]      = w0;
        *(float4*)&Bs[rb + 8][nb]  = w1;
        __syncthreads();
        #pragma unroll
        for (int kk = 0; kk < 16; kk++) {
            ulonglong2 b01 = *(const ulonglong2*)&Bs[kk][tn * 8];
            ulonglong2 b23 = *(const ulonglong2*)&Bs[kk][tn * 8 + 4];
            #pragma unroll
            for (int i = 0; i < 8; i++) {
                ull ad = dup2f(As[tm * 8 + i][kk]);
                ffma2(acc2[i][0], ad, b01.x);
                ffma2(acc2[i][1], ad, b01.y);
                ffma2(acc2[i][2], ad, b23.x);
                ffma2(acc2[i][3], ad, b23.y);
            }
        }
    }

    float bias[8];
    #pragma unroll
    for (int jj = 0; jj < 8; jj++) {
        int c = Nbase + tn * 8 + jj;
        bias[jj] = (c < 512) ? bzr[c] : bh[c - 512];
    }

    #pragma unroll
    for (int i = 0; i < 8; i++) {
        int r = Mbase + tm * 8 + i;   // r = b*1024 + t
        int b = r >> 10;
        int t = r & 1023;
        float* dst = &g_xzh[(size_t)((t << 7) + b) * 768 + Nbase + tn * 8];
        float c[8];
        #pragma unroll
        for (int p = 0; p < 4; p++) unpack2(acc2[i][p], c[2 * p], c[2 * p + 1]);
        float4 v0, v1;
        v0.x = c[0] + bias[0]; v0.y = c[1] + bias[1];
        v0.z = c[2] + bias[2]; v0.w = c[3] + bias[3];
        v1.x = c[4] + bias[4]; v1.y = c[5] + bias[5];
        v1.z = c[6] + bias[6]; v1.w = c[7] + bias[7];
        *(float4*)dst       = v0;
        *(float4*)(dst + 4) = v1;
    }
}

// ---------------------------------------------------------------------------
// Kernel 2: GRU recurrence. 32 clusters x 4 CTAs x 512 threads (16 warps).
// Cluster owns 4 batch rows. CTA rank r holds U_zr cols [128r,128r+128)
// (128 KB) and U_h cols [64r,64r+64) (64 KB) in SMEM.
// Warp (cg, ks): cg = wid>>3 column-group, ks = wid&7 k-slice of 32.
// DSMEM routing and sync structure identical to the proven R4 kernel.
// ---------------------------------------------------------------------------
#define OFF_WZR 0         // float2[256][64]  128 KB  U_zr slice, k-major (float2 = col pair)
#define OFF_WH  131072    // float [256][64]   64 KB  U_h  slice, k-major
#define OFF_RED 196608    // ull  [2048]       16 KB  partials (p1: [2][8][64]x2, p2: [8][64]x2)
#define OFF_H   212992    // float4[256]        4 KB  h (rows 0..3 per hidden col)
#define OFF_RH  217088    // float4[256]        4 KB  R*h
#define OFF_Z   221184    // float4[64]         1 KB  Z slice for this CTA's S cols
#define SMEM_BYTES 222208

extern "C" __global__ void __launch_bounds__(512, 1) __cluster_dims__(4, 1, 1)
gru_recur4w(const float* __restrict__ Uzr,
            const float* __restrict__ Uh,
            float* __restrict__ out)
{
    extern __shared__ char smem[];
    float2* wzr2  = (float2*)(smem + OFF_WZR);
    float*  wh_s  = (float*)(smem + OFF_WH);
    ull*    red_u = (ull*)(smem + OFF_RED);
    float4* h4    = (float4*)(smem + OFF_H);
    float4* rh4   = (float4*)(smem + OFF_RH);
    float4* z4    = (float4*)(smem + OFF_Z);
    ull*    h_u   = (ull*)h4;
    ull*    rh_u  = (ull*)rh4;

    const int tid  = threadIdx.x;
    const int wid  = tid >> 5;
    const int lane = tid & 31;
    const int cg   = wid >> 3;        // column group 0/1
    const int ks   = wid & 7;         // k-slice (32 k each)
    const uint32_t crank = blockIdx.x & 3;
    const int r0 = (blockIdx.x >> 2) * 4;   // first batch row of this cluster

    // ---- prologue: weight slices -> smem, h = 0 ----
    {
        const float2* Uzr2g = (const float2*)Uzr;   // [256][256] float2 view
        #pragma unroll 4
        for (int idx = tid; idx < 16384; idx += 512)
            wzr2[idx] = Uzr2g[(idx >> 6) * 256 + crank * 64 + (idx & 63)];
        #pragma unroll 4
        for (int idx = tid; idx < 16384; idx += 512)
            wh_s[idx] = Uh[(idx >> 6) * 256 + crank * 64 + (idx & 63)];
        if (tid < 256) h4[tid] = make_float4(0.f, 0.f, 0.f, 0.f);
    }
    __syncthreads();
    cluster_sync_();

    // DSMEM peer addresses
    uint32_t h_base = smem_u32(h4), rh_base = smem_u32(rh4), z_base = smem_u32(z4);
    uint32_t h_r[4], rh_r[4], z_r[4];
    #pragma unroll
    for (uint32_t r = 0; r < 4; r++) {
        h_r[r]  = mapa_rank(h_base, r);
        rh_r[r] = mapa_rank(rh_base, r);
        z_r[r]  = mapa_rank(z_base, r);
    }

    // reduce-thread coords: reduce1 uses tid<128 -> (i = tid>>6, pr = tid&63, col = 2pr+i)
    const int rzi  = tid >> 6;
    const int rzpr = tid & 63;
    const int rzcol = 2 * rzpr + rzi;

    for (int t = 0; t < 1024; t++) {
        // ---- prefetch this step's xz / xh (DRAM; consumed at the reduces) ----
        const size_t tb = (size_t)((t << 7) + r0) * 768;
        float xz0 = 0.f, xz1 = 0.f, xz2 = 0.f, xz3 = 0.f;
        float xh0 = 0.f, xh1 = 0.f, xh2 = 0.f, xh3 = 0.f;
        if (tid < 128) {
            const float* p = g_xzh + tb + crank * 128 + rzcol;
            xz0 = p[0]; xz1 = p[768]; xz2 = p[1536]; xz3 = p[2304];
        }
        if (tid < 64) {
            const float* p = g_xzh + tb + 512 + crank * 64 + tid;
            xh0 = p[0]; xh1 = p[768]; xh2 = p[1536]; xh3 = p[2304];
        }

        // ---- phase 1: partial z[4 rows][128 local cols] ----
        // warp (cg,ks): lane owns col pair (2*(cg*32+lane), +1), k in [32ks, 32ks+32)
        ull a01_0 = 0, a23_0 = 0, a01_1 = 0, a23_1 = 0;
        {
            const float2* wp = wzr2 + (ks * 32) * 64 + cg * 32 + lane;
            const ull*    hp = h_u + (ks * 32) * 2;
            #pragma unroll 8
            for (int kk = 0; kk < 32; kk++) {
                float2 w = wp[kk * 64];
                ulonglong2 hv = *(const ulonglong2*)(hp + 2 * kk);   // (r0,r1),(r2,r3)
                ull w0 = dup2f(w.x), w1 = dup2f(w.y);
                ffma2(a01_0, w0, hv.x); ffma2(a23_0, w0, hv.y);
                ffma2(a01_1, w1, hv.x); ffma2(a23_1, w1, hv.y);
            }
        }
        {
            int pr = cg * 32 + lane;
            ulonglong2 v0; v0.x = a01_0; v0.y = a23_0;
            ulonglong2 v1; v1.x = a01_1; v1.y = a23_1;
            *(ulonglong2*)&red_u[ks * 128 + pr * 2]        = v0;   // col 2pr
            *(ulonglong2*)&red_u[1024 + ks * 128 + pr * 2] = v1;   // col 2pr+1
        }
        __syncthreads();

        // ---- reduce1 + gates + DSMEM routing (tid < 128) ----
        if (tid < 128) {
            const ull* P = red_u + rzi * 1024 + rzpr * 2;
            float s0 = xz0, s1 = xz1, s2 = xz2, s3 = xz3;
            #pragma unroll
            for (int k2 = 0; k2 < 8; k2++) {
                ulonglong2 v = *(const ulonglong2*)(P + k2 * 128);
                float p0, p1, p2, p3;
                unpack2(v.x, p0, p1); unpack2(v.y, p2, p3);
                s0 += p0; s1 += p1; s2 += p2; s3 += p3;
            }
            float g0 = sigf(s0), g1 = sigf(s1), g2 = sigf(s2), g3 = sigf(s3);
            if (crank < 2) {
                // update gate Z: route to the CTA owning these S columns
                uint32_t dest = 2 * crank + (uint32_t)(rzcol >> 6);
                st_cluster_f4(z_r[dest] + (uint32_t)(rzcol & 63) * 16,
                              make_float4(g0, g1, g2, g3));
            } else {
                // reset gate R: rh = R .* h, broadcast to all 4 CTAs
                int ch = ((int)crank - 2) * 128 + rzcol;     // hidden col
                float4 hv = h4[ch];
                float4 rh;
                rh.x = g0 * hv.x; rh.y = g1 * hv.y; rh.z = g2 * hv.z; rh.w = g3 * hv.w;
                uint32_t off = (uint32_t)ch * 16;
                #pragma unroll
                for (uint32_t r = 0; r < 4; r++)
                    st_cluster_f4(rh_r[r] + off, rh);
            }
        }
        cluster_sync_();

        // ---- phase 2: partial S[4 rows][64 local cols] ----
        // warp (cg,ks): lane owns col cg*32+lane, k in [32ks, 32ks+32)
        ull b01 = 0, b23 = 0;
        {
            const float* wp2 = wh_s + (ks * 32) * 64 + cg * 32 + lane;
            const ull*   rp  = rh_u + (ks * 32) * 2;
            #pragma unroll 8
            for (int kk = 0; kk < 32; kk++) {
                float w = wp2[kk * 64];
                ulonglong2 rv = *(const ulonglong2*)(rp + 2 * kk);
                ull wd = dup2f(w);
                ffma2(b01, wd, rv.x); ffma2(b23, wd, rv.y);
            }
        }
        {
            int c = cg * 32 + lane;
            ulonglong2 v; v.x = b01; v.y = b23;
            *(ulonglong2*)&red_u[ks * 128 + c * 2] = v;
        }
        __syncthreads();

        // ---- reduce2 + combine + h broadcast (tid < 64) ----
        if (tid < 64) {
            const ull* P = red_u + tid * 2;
            float s0 = xh0, s1 = xh1, s2 = xh2, s3 = xh3;
            #pragma unroll
            for (int k2 = 0; k2 < 8; k2++) {
                ulonglong2 v = *(const ulonglong2*)(P + k2 * 128);
                float p0, p1, p2, p3;
                unpack2(v.x, p0, p1); unpack2(v.y, p2, p3);
                s0 += p0; s1 += p1; s2 += p2; s3 += p3;
            }
            float S0 = tanhfast(s0), S1 = tanhfast(s1);
            float S2 = tanhfast(s2), S3 = tanhfast(s3);
            float4 Z = z4[tid];
            int gcol = (int)crank * 64 + tid;
            float4 hv = h4[gcol];
            float4 hn;
            hn.x = fmaf(Z.x, S0 - hv.x, hv.x);
            hn.y = fmaf(Z.y, S1 - hv.y, hv.y);
            hn.z = fmaf(Z.z, S2 - hv.z, hv.z);
            hn.w = fmaf(Z.w, S3 - hv.w, hv.w);
            uint32_t off = (uint32_t)gcol * 16;
            #pragma unroll
            for (uint32_t r = 0; r < 4; r++)
                st_cluster_f4(h_r[r] + off, hn);
        }
        cluster_sync_();
    }

    // ---- epilogue: rank 0 writes the 4 rows ----
    if (crank == 0 && tid < 256) {
        float4 hv = h4[tid];
        out[(r0 + 0) * 256 + tid] = hv.x;
        out[(r0 + 1) * 256 + tid] = hv.y;
        out[(r0 + 2) * 256 + tid] = hv.z;
        out[(r0 + 3) * 256 + tid] = hv.w;
    }
}

// ---------------------------------------------------------------------------
extern "C" void kernel_launch(void* const* d_in, const int* in_sizes, int n_in,
                              void* d_out, int out_size)
{
    (void)in_sizes; (void)n_in; (void)out_size;
    const float* x   = (const float*)d_in[0];
    const float* Wzr = (const float*)d_in[1];
    const float* Uzr = (const float*)d_in[2];
    const float* bzr = (const float*)d_in[3];
    const float* Wh  = (const float*)d_in[4];
    const float* Uh  = (const float*)d_in[5];
    const float* bh  = (const float*)d_in[6];

    dim3 ggrid(6, 1024);
    proj_gemm<<<ggrid, 256>>>(x, Wzr, Wh, bzr, bh);

    cudaFuncSetAttribute(gru_recur4w,
                         cudaFuncAttributeMaxDynamicSharedMemorySize, SMEM_BYTES);
    gru_recur4w<<<128, 512, SMEM_BYTES>>>(Uzr, Uh, (float*)d_out);
}

// round 9
// speedup vs baseline: 3.1184x; 1.2300x over previous
#include <cuda_runtime.h>
#include <math.h>
#include <stdint.h>

typedef unsigned long long ull;

// Scratch: projected inputs [t][b][768] (xz cols 0..511 incl bias, xh cols 512..767)
__device__ float g_xzh[131072 * 768];  // 402 MB static scratch

// ---------------------------------------------------------------------------
// helpers
// ---------------------------------------------------------------------------
__device__ __forceinline__ ull dup2f(float x) {
    ull r; asm("mov.b64 %0, {%1, %1};" : "=l"(r) : "f"(x)); return r;
}
__device__ __forceinline__ void unpack2(ull v, float& x, float& y) {
    asm("mov.b64 {%0, %1}, %2;" : "=f"(x), "=f"(y) : "l"(v));
}
__device__ __forceinline__ void ffma2(ull& d, ull a, ull b) {
    asm("fma.rn.f32x2 %0, %1, %2, %0;" : "+l"(d) : "l"(a), "l"(b));
}
__device__ __forceinline__ uint32_t smem_u32(const void* p) {
    return (uint32_t)__cvta_generic_to_shared(p);
}
__device__ __forceinline__ uint32_t mapa_rank(uint32_t addr, uint32_t rank) {
    uint32_t r; asm("mapa.shared::cluster.u32 %0, %1, %2;" : "=r"(r) : "r"(addr), "r"(rank));
    return r;
}
__device__ __forceinline__ void st_cluster_f4(uint32_t addr, float4 v) {
    asm volatile("st.shared::cluster.v4.f32 [%0], {%1,%2,%3,%4};"
                 :: "r"(addr), "f"(v.x), "f"(v.y), "f"(v.z), "f"(v.w) : "memory");
}
__device__ __forceinline__ void cluster_sync_() {
    asm volatile("barrier.cluster.arrive.aligned;" ::: "memory");
    asm volatile("barrier.cluster.wait.aligned;" ::: "memory");
}
__device__ __forceinline__ float sigf(float x) {
    return __fdividef(1.f, 1.f + __expf(-x));
}
__device__ __forceinline__ float tanhfast(float x) {
    float a = fabsf(x);
    float e = __expf(2.f * a);
    float r = 1.f - __fdividef(2.f, e + 1.f);
    return copysignf(r, x);
}

// ---------------------------------------------------------------------------
// Kernel 1: projection GEMM (f32x2 microtile), unchanged (measured ~1.1 ms)
// ---------------------------------------------------------------------------
__global__ __launch_bounds__(256, 2) void proj_gemm(
    const float* __restrict__ x,
    const float* __restrict__ Wzr,
    const float* __restrict__ Wh,
    const float* __restrict__ bzr,
    const float* __restrict__ bh)
{
    __shared__ float As[128][16];
    __shared__ float Bs[16][128];

    const int tid = threadIdx.x;
    const int tm = tid >> 4;
    const int tn = tid & 15;
    const int Mbase = blockIdx.y * 128;
    const int Nbase = blockIdx.x * 128;

    const bool isZr = (Nbase < 512);
    const float* __restrict__ W = isZr ? Wzr : Wh;
    const int ldw  = isZr ? 512 : 256;
    const int wcol = isZr ? Nbase : (Nbase - 512);

    ull acc2[8][4];
    #pragma unroll
    for (int i = 0; i < 8; i++)
        #pragma unroll
        for (int p = 0; p < 4; p++) acc2[i][p] = 0ull;

    const int ra = tid >> 2;
    const int ka = (tid & 3) << 2;
    const int rb = tid >> 5;
    const int nb = (tid & 31) << 2;

    for (int kt = 0; kt < 256; kt += 16) {
        float4 a0 = *(const float4*)&x[(size_t)(Mbase + ra)      * 256 + kt + ka];
        float4 a1 = *(const float4*)&x[(size_t)(Mbase + ra + 64) * 256 + kt + ka];
        float4 w0 = *(const float4*)&W[(size_t)(kt + rb)     * ldw + wcol + nb];
        float4 w1 = *(const float4*)&W[(size_t)(kt + rb + 8) * ldw + wcol + nb];
        __syncthreads();
        *(float4*)&As[ra][ka]      = a0;
        *(float4*)&As[ra + 64][ka] = a1;
        *(float4*)&Bs[rb][nb]      = w0;
        *(float4*)&Bs[rb + 8][nb]  = w1;
        __syncthreads();
        #pragma unroll
        for (int kk = 0; kk < 16; kk++) {
            ulonglong2 b01 = *(const ulonglong2*)&Bs[kk][tn * 8];
            ulonglong2 b23 = *(const ulonglong2*)&Bs[kk][tn * 8 + 4];
            #pragma unroll
            for (int i = 0; i < 8; i++) {
                ull ad = dup2f(As[tm * 8 + i][kk]);
                ffma2(acc2[i][0], ad, b01.x);
                ffma2(acc2[i][1], ad, b01.y);
                ffma2(acc2[i][2], ad, b23.x);
                ffma2(acc2[i][3], ad, b23.y);
            }
        }
    }

    float bias[8];
    #pragma unroll
    for (int jj = 0; jj < 8; jj++) {
        int c = Nbase + tn * 8 + jj;
        bias[jj] = (c < 512) ? bzr[c] : bh[c - 512];
    }

    #pragma unroll
    for (int i = 0; i < 8; i++) {
        int r = Mbase + tm * 8 + i;   // r = b*1024 + t
        int b = r >> 10;
        int t = r & 1023;
        float* dst = &g_xzh[(size_t)((t << 7) + b) * 768 + Nbase + tn * 8];
        float c[8];
        #pragma unroll
        for (int p = 0; p < 4; p++) unpack2(acc2[i][p], c[2 * p], c[2 * p + 1]);
        float4 v0, v1;
        v0.x = c[0] + bias[0]; v0.y = c[1] + bias[1];
        v0.z = c[2] + bias[2]; v0.w = c[3] + bias[3];
        v1.x = c[4] + bias[4]; v1.y = c[5] + bias[5];
        v1.z = c[6] + bias[6]; v1.w = c[7] + bias[7];
        *(float4*)dst       = v0;
        *(float4*)(dst + 4) = v1;
    }
}

// ---------------------------------------------------------------------------
// Kernel 2: GRU recurrence. 32 clusters x 4 CTAs x 256 threads (8 warps) —
// the proven R4 skeleton, but WEIGHTS LIVE IN REGISTERS (constant across all
// 1024 steps): per thread, U_zr 32k x 4 cols (128 floats) + U_h 32k x 2 cols
// (64 floats). SMEM holds only h / R*h / Z / reduction partials (~25 KB).
// Per-step LDS traffic drops from 192 KB to a few KB of broadcasts.
// ---------------------------------------------------------------------------
extern "C" __global__ void __launch_bounds__(256, 1) __cluster_dims__(4, 1, 1)
gru_recur_reg(const float* __restrict__ Uzr,
              const float* __restrict__ Uh,
              float* __restrict__ out)
{
    __shared__ float4 red4[8 * 128];   // 16 KB partials (phase2 reuses first 8 KB)
    __shared__ float4 h4[256];         // h, rows 0..3 per hidden col
    __shared__ float4 rh4[256];        // R*h
    __shared__ float4 z4[64];          // Z slice for this CTA's S cols

    const int tid  = threadIdx.x;
    const int wid  = tid >> 5;        // 0..7 : k-slice [32w, 32w+32)
    const int lane = tid & 31;
    const uint32_t crank = blockIdx.x & 3;
    const int r0 = (blockIdx.x >> 2) * 4;   // first batch row of this cluster

    // ---- prologue: weight slices -> REGISTERS, h = 0 ----
    // phase1: z-cols 4*lane .. 4*lane+3 (local, global = crank*128 + ...)
    // phase2: S-cols 2*lane .. 2*lane+1 (local, global = crank*64 + ...)
    float wz[32][4];
    float wh[32][2];
    {
        const float* pz = Uzr + (size_t)(wid * 32) * 512 + crank * 128 + 4 * lane;
        #pragma unroll
        for (int kk = 0; kk < 32; kk++)
            *(float4*)wz[kk] = *(const float4*)(pz + (size_t)kk * 512);
        const float* ph = Uh + (size_t)(wid * 32) * 256 + crank * 64 + 2 * lane;
        #pragma unroll
        for (int kk = 0; kk < 32; kk++)
            *(float2*)wh[kk] = *(const float2*)(ph + (size_t)kk * 256);
    }
    h4[tid] = make_float4(0.f, 0.f, 0.f, 0.f);
    __syncthreads();
    cluster_sync_();

    // DSMEM peer addresses
    uint32_t h_base = smem_u32(h4), rh_base = smem_u32(rh4), z_base = smem_u32(z4);
    uint32_t h_r[4], rh_r[4], z_r[4];
    #pragma unroll
    for (uint32_t r = 0; r < 4; r++) {
        h_r[r]  = mapa_rank(h_base, r);
        rh_r[r] = mapa_rank(rh_base, r);
        z_r[r]  = mapa_rank(z_base, r);
    }

    const ull* h_u  = (const ull*)h4;
    const ull* rh_u = (const ull*)rh4;

    #pragma unroll 1
    for (int t = 0; t < 1024; t++) {
        // ---- prefetch this step's xz / xh (DRAM; consumed at the reduces) ----
        const size_t tb = (size_t)((t << 7) + r0) * 768;
        float xz0 = 0.f, xz1 = 0.f, xz2 = 0.f, xz3 = 0.f;
        float xh0 = 0.f, xh1 = 0.f, xh2 = 0.f, xh3 = 0.f;
        if (tid < 128) {
            const float* p = g_xzh + tb + crank * 128 + tid;
            xz0 = p[0]; xz1 = p[768]; xz2 = p[1536]; xz3 = p[2304];
        }
        if (tid < 64) {
            const float* p = g_xzh + tb + 512 + crank * 64 + tid;
            xh0 = p[0]; xh1 = p[768]; xh2 = p[1536]; xh3 = p[2304];
        }

        // ---- phase 1: partial z[4 rows][4 cols/lane], k in [32w, 32w+32) ----
        ull a01[4] = {0, 0, 0, 0}, a23[4] = {0, 0, 0, 0};
        {
            const ull* hp = h_u + wid * 64;
            #pragma unroll
            for (int kk = 0; kk < 32; kk++) {
                ulonglong2 hv = *(const ulonglong2*)(hp + 2 * kk);  // rows (0,1),(2,3)
                ull w0 = dup2f(wz[kk][0]), w1 = dup2f(wz[kk][1]);
                ull w2 = dup2f(wz[kk][2]), w3 = dup2f(wz[kk][3]);
                ffma2(a01[0], w0, hv.x); ffma2(a23[0], w0, hv.y);
                ffma2(a01[1], w1, hv.x); ffma2(a23[1], w1, hv.y);
                ffma2(a01[2], w2, hv.x); ffma2(a23[2], w2, hv.y);
                ffma2(a01[3], w3, hv.x); ffma2(a23[3], w3, hv.y);
            }
        }
        #pragma unroll
        for (int i = 0; i < 4; i++) {
            int col = 4 * lane + i;
            int sc = col ^ ((col >> 2) & 7);                 // conflict-free swizzle
            ulonglong2 v; v.x = a01[i]; v.y = a23[i];
            *(ulonglong2*)&red4[wid * 128 + sc] = v;
        }
        __syncthreads();

        // ---- reduce1 + gates + DSMEM routing (tid < 128, col = tid) ----
        if (tid < 128) {
            int sc = tid ^ ((tid >> 2) & 7);
            float4 s = red4[sc];
            #pragma unroll
            for (int w = 1; w < 8; w++) {
                float4 p = red4[w * 128 + sc];
                s.x += p.x; s.y += p.y; s.z += p.z; s.w += p.w;
            }
            s.x += xz0; s.y += xz1; s.z += xz2; s.w += xz3;
            float4 g;
            g.x = sigf(s.x); g.y = sigf(s.y); g.z = sigf(s.z); g.w = sigf(s.w);
            if (crank < 2) {
                // update gate Z: route to the CTA owning these S columns
                uint32_t dest = 2 * crank + (uint32_t)(tid >> 6);
                st_cluster_f4(z_r[dest] + (uint32_t)(tid & 63) * 16, g);
            } else {
                // reset gate R: rh = R .* h, broadcast to all 4 CTAs
                int ch = ((int)crank - 2) * 128 + tid;       // hidden col
                float4 hv = h4[ch];
                float4 rh;
                rh.x = g.x * hv.x; rh.y = g.y * hv.y;
                rh.z = g.z * hv.z; rh.w = g.w * hv.w;
                uint32_t off = (uint32_t)ch * 16;
                #pragma unroll
                for (uint32_t r = 0; r < 4; r++)
                    st_cluster_f4(rh_r[r] + off, rh);
            }
        }
        cluster_sync_();

        // ---- phase 2: partial S[4 rows][2 cols/lane] ----
        ull b01[2] = {0, 0}, b23[2] = {0, 0};
        {
            const ull* rp = rh_u + wid * 64;
            #pragma unroll
            for (int kk = 0; kk < 32; kk++) {
                ulonglong2 rv = *(const ulonglong2*)(rp + 2 * kk);
                ull w0 = dup2f(wh[kk][0]), w1 = dup2f(wh[kk][1]);
                ffma2(b01[0], w0, rv.x); ffma2(b23[0], w0, rv.y);
                ffma2(b01[1], w1, rv.x); ffma2(b23[1], w1, rv.y);
            }
        }
        #pragma unroll
        for (int i = 0; i < 2; i++) {
            int col = 2 * lane + i;
            int sc = col ^ ((col >> 1) & 7);
            ulonglong2 v; v.x = b01[i]; v.y = b23[i];
            *(ulonglong2*)&red4[wid * 64 + sc] = v;
        }
        __syncthreads();

        // ---- reduce2 + combine + h broadcast (tid < 64, col = tid) ----
        if (tid < 64) {
            int sc = tid ^ ((tid >> 1) & 7);
            float4 s = red4[sc];
            #pragma unroll
            for (int w = 1; w < 8; w++) {
                float4 p = red4[w * 64 + sc];
                s.x += p.x; s.y += p.y; s.z += p.z; s.w += p.w;
            }
            float S0 = tanhfast(s.x + xh0), S1 = tanhfast(s.y + xh1);
            float S2 = tanhfast(s.z + xh2), S3 = tanhfast(s.w + xh3);
            float4 Z = z4[tid];
            int gcol = (int)crank * 64 + tid;
            float4 hv = h4[gcol];
            float4 hn;
            hn.x = fmaf(Z.x, S0 - hv.x, hv.x);
            hn.y = fmaf(Z.y, S1 - hv.y, hv.y);
            hn.z = fmaf(Z.z, S2 - hv.z, hv.z);
            hn.w = fmaf(Z.w, S3 - hv.w, hv.w);
            uint32_t off = (uint32_t)gcol * 16;
            #pragma unroll
            for (uint32_t r = 0; r < 4; r++)
                st_cluster_f4(h_r[r] + off, hn);
        }
        cluster_sync_();
    }

    // ---- epilogue: rank 0 writes the 4 rows ----
    if (crank == 0) {
        float4 hv = h4[tid];
        out[(r0 + 0) * 256 + tid] = hv.x;
        out[(r0 + 1) * 256 + tid] = hv.y;
        out[(r0 + 2) * 256 + tid] = hv.z;
        out[(r0 + 3) * 256 + tid] = hv.w;
    }
}

// ---------------------------------------------------------------------------
extern "C" void kernel_launch(void* const* d_in, const int* in_sizes, int n_in,
                              void* d_out, int out_size)
{
    (void)in_sizes; (void)n_in; (void)out_size;
    const float* x   = (const float*)d_in[0];
    const float* Wzr = (const float*)d_in[1];
    const float* Uzr = (const float*)d_in[2];
    const float* bzr = (const float*)d_in[3];
    const float* Wh  = (const float*)d_in[4];
    const float* Uh  = (const float*)d_in[5];
    const float* bh  = (const float*)d_in[6];

    dim3 ggrid(6, 1024);
    proj_gemm<<<ggrid, 256>>>(x, Wzr, Wh, bzr, bh);

    gru_recur_reg<<<128, 256>>>(Uzr, Uh, (float*)d_out);
}